// round 6
// baseline (speedup 1.0000x reference)
#include <cuda_runtime.h>
#include <cuda_bf16.h>
#include <cstdint>

#define BDIM 32
#define CDIM 512
#define KDIM 32
#define NPIX 4096   // 64*64

// w packed per element: u32 = { bf16 hi (low 16b), bf16 lo (high 16b) }
__device__ unsigned g_whl[BDIM * KDIM * NPIX];   // 16 MiB
__device__ float g_wsum[BDIM * 16 * KDIM];       // [b][tile][k]

// ---------- packed fp32x2 helpers (k1) ----------
__device__ __forceinline__ unsigned long long fma2(unsigned long long a,
                                                   unsigned long long b,
                                                   unsigned long long c) {
    unsigned long long d;
    asm("fma.rn.f32x2 %0, %1, %2, %3;" : "=l"(d) : "l"(a), "l"(b), "l"(c));
    return d;
}
__device__ __forceinline__ float2 upk(unsigned long long v) {
    float2 r;
    asm("mov.b64 {%0, %1}, %2;" : "=f"(r.x), "=f"(r.y) : "l"(v));
    return r;
}
// pack {lo_elem -> low 16, hi_elem -> high 16}
__device__ __forceinline__ unsigned pk_bf16x2(float lo, float hi) {
    unsigned r;
    asm("cvt.rn.bf16x2.f32 %0, %1, %2;" : "=r"(r) : "f"(hi), "f"(lo));
    return r;
}

// ---------- warp mma (legacy HMMA path, no 'a'-feature needed) ----------
__device__ __forceinline__ void mma_bf16(float* d,
                                         unsigned a0, unsigned a1,
                                         unsigned a2, unsigned a3,
                                         unsigned b0, unsigned b1) {
    asm volatile(
        "mma.sync.aligned.m16n8k16.row.col.f32.bf16.bf16.f32 "
        "{%0,%1,%2,%3}, {%4,%5,%6,%7}, {%8,%9}, {%0,%1,%2,%3};"
        : "+f"(d[0]), "+f"(d[1]), "+f"(d[2]), "+f"(d[3])
        : "r"(a0), "r"(a1), "r"(a2), "r"(a3), "r"(b0), "r"(b1));
}

// ============================================================================
// Kernel 1: fused dist-GEMM (fp32x2) + softmax + packed bf16 hi/lo w + wsum
// grid (16, 32): 256-pixel n-tile, b. 256 threads.
// ============================================================================
__global__ __launch_bounds__(256) void enc_k1(
    const float* __restrict__ x,
    const float* __restrict__ cw,
    const float* __restrict__ scale)
{
    // pool: [0, 8320) x_s[32][256] (GEMM) then dist_s[32][260] (epilogue)
    //       [8320, 10496) cwd_s[32][68]
    __shared__ __align__(16) float pool[8320 + 2176];
    float* x_s    = pool;
    float* dist_s = pool;
    unsigned* dist_su = (unsigned*)pool;
    float* cwd_s  = pool + 8320;
    __shared__ float x2_s[256];
    __shared__ float c2_s[KDIM];
    __shared__ float sc_s[KDIM];

    const int t    = threadIdx.x;
    const int b    = blockIdx.y;
    const int n0   = blockIdx.x * 256;
    const int lane = t & 31, w = t >> 5;
    const int kg = lane >> 3, ng = lane & 7;
    const int kgp = w >> 2,  ngp = w & 3;
    const int nbase = ngp * 64;

    // ---- c2[k] precompute ----
    {
        const int k = t >> 3, seg = t & 7;
        const float4* p = (const float4*)(cw + k * CDIM + seg * 64);
        float s = 0.f;
        #pragma unroll
        for (int i = 0; i < 16; ++i) {
            float4 v = p[i];
            s += v.x * v.x + v.y * v.y + v.z * v.z + v.w * v.w;
        }
        x2_s[t] = s;
        if (t < KDIM) sc_s[t] = scale[t];
        __syncthreads();
        if (t < KDIM) {
            float s2 = 0.f;
            #pragma unroll
            for (int j = 0; j < 8; ++j) s2 += x2_s[t * 8 + j];
            c2_s[t] = s2;
        }
    }

    unsigned long long acc[16];
    #pragma unroll
    for (int i = 0; i < 16; ++i) acc[i] = 0ull;
    float x2a = 0.f;

    const float* xb = x + (size_t)b * CDIM * NPIX + n0;

    for (int c0 = 0; c0 < CDIM; c0 += 32) {
        __syncthreads();
        #pragma unroll
        for (int i = 0; i < 8; ++i) {
            int idx = t + 256 * i;
            int cb = idx >> 6, nq = idx & 63;
            float4 v = *(const float4*)(xb + (size_t)(c0 + cb) * NPIX + 4 * nq);
            *(float4*)(x_s + cb * 256 + 4 * nq) = v;
        }
        {
            int k = t >> 3, cq = t & 7;
            float4 v = *(const float4*)(cw + k * CDIM + c0 + 4 * cq);
            float vv[4] = {v.x, v.y, v.z, v.w};
            #pragma unroll
            for (int j = 0; j < 4; ++j)
                *(float2*)(cwd_s + (4 * cq + j) * 68 + 2 * k) =
                    make_float2(vv[j], vv[j]);
        }
        __syncthreads();

        #pragma unroll 8
        for (int cb = 0; cb < 32; ++cb) {
            float v = x_s[cb * 256 + t];
            x2a = fmaf(v, v, x2a);
        }

        #pragma unroll 4
        for (int cb = 0; cb < 32; ++cb) {
            ulonglong2 xA = *(const ulonglong2*)(x_s + cb * 256 + nbase + 4 * ng);
            ulonglong2 xB = *(const ulonglong2*)(x_s + cb * 256 + nbase + 32 + 4 * ng);
            ulonglong2 wA = *(const ulonglong2*)(cwd_s + cb * 68 + kgp * 32 + 8 * kg);
            ulonglong2 wB = *(const ulonglong2*)(cwd_s + cb * 68 + kgp * 32 + 8 * kg + 4);
            acc[0]  = fma2(xA.x, wA.x, acc[0]);
            acc[1]  = fma2(xA.y, wA.x, acc[1]);
            acc[2]  = fma2(xB.x, wA.x, acc[2]);
            acc[3]  = fma2(xB.y, wA.x, acc[3]);
            acc[4]  = fma2(xA.x, wA.y, acc[4]);
            acc[5]  = fma2(xA.y, wA.y, acc[5]);
            acc[6]  = fma2(xB.x, wA.y, acc[6]);
            acc[7]  = fma2(xB.y, wA.y, acc[7]);
            acc[8]  = fma2(xA.x, wB.x, acc[8]);
            acc[9]  = fma2(xA.y, wB.x, acc[9]);
            acc[10] = fma2(xB.x, wB.x, acc[10]);
            acc[11] = fma2(xB.y, wB.x, acc[11]);
            acc[12] = fma2(xA.x, wB.y, acc[12]);
            acc[13] = fma2(xA.y, wB.y, acc[13]);
            acc[14] = fma2(xB.x, wB.y, acc[14]);
            acc[15] = fma2(xB.y, wB.y, acc[15]);
        }
    }

    __syncthreads();           // x_s reads complete before reuse as dist_s
    x2_s[t] = x2a;
    __syncthreads();

    // dist -> smem [k][260-pitch]
    const int nA = nbase + 4 * ng;
    #pragma unroll
    for (int kk = 0; kk < 4; ++kk) {
        const int k = kgp * 16 + 4 * kg + kk;
        const float sck = sc_s[k], c2k = c2_s[k];
        float2 p0 = upk(acc[kk * 4 + 0]);
        float2 p1 = upk(acc[kk * 4 + 1]);
        float2 p2 = upk(acc[kk * 4 + 2]);
        float2 p3 = upk(acc[kk * 4 + 3]);
        float4 dA, dB;
        dA.x = sck * (x2_s[nA + 0] - 2.f * p0.x + c2k);
        dA.y = sck * (x2_s[nA + 1] - 2.f * p0.y + c2k);
        dA.z = sck * (x2_s[nA + 2] - 2.f * p1.x + c2k);
        dA.w = sck * (x2_s[nA + 3] - 2.f * p1.y + c2k);
        dB.x = sck * (x2_s[nA + 32] - 2.f * p2.x + c2k);
        dB.y = sck * (x2_s[nA + 33] - 2.f * p2.y + c2k);
        dB.z = sck * (x2_s[nA + 34] - 2.f * p3.x + c2k);
        dB.w = sck * (x2_s[nA + 35] - 2.f * p3.y + c2k);
        *(float4*)(dist_s + k * 260 + nA)      = dA;
        *(float4*)(dist_s + k * 260 + nA + 32) = dB;
    }
    __syncthreads();

    // per-pixel softmax (pixel = t), keep w in regs
    float d[KDIM];
    {
        #pragma unroll
        for (int k = 0; k < KDIM; ++k) d[k] = dist_s[k * 260 + t];
        float m = d[0];
        #pragma unroll
        for (int k = 1; k < KDIM; ++k) m = fmaxf(m, d[k]);
        float sum = 0.f;
        #pragma unroll
        for (int k = 0; k < KDIM; ++k) { d[k] = __expf(d[k] - m); sum += d[k]; }
        const float inv = 1.0f / sum;
        #pragma unroll
        for (int k = 0; k < KDIM; ++k) d[k] *= inv;
    }
    __syncthreads();
    // pass 1: fp32 w -> dist_s for wsum
    #pragma unroll
    for (int k = 0; k < KDIM; ++k) dist_s[k * 260 + t] = d[k];
    __syncthreads();

    if (t < KDIM) {
        float s = 0.f;
        #pragma unroll 8
        for (int j = 0; j < 256; ++j) s += dist_s[t * 260 + j];
        g_wsum[((size_t)b * 16 + blockIdx.x) * KDIM + t] = s;
    }
    __syncthreads();

    // pass 2: packed {hi,lo} words -> smem
    #pragma unroll
    for (int k = 0; k < KDIM; ++k) {
        float wv = d[k];
        __nv_bfloat16 h = __float2bfloat16(wv);
        float hf = __bfloat162float(h);
        __nv_bfloat16 l = __float2bfloat16(wv - hf);
        unsigned word = (unsigned)__bfloat16_as_ushort(h) |
                        ((unsigned)__bfloat16_as_ushort(l) << 16);
        dist_su[k * 260 + t] = word;
    }
    __syncthreads();

    // pass 3: vectorized global store (STG.128)
    #pragma unroll
    for (int j = 0; j < 8; ++j) {
        int idx = t + 256 * j;
        int k = idx >> 6, nq = (idx & 63) * 4;
        uint4 v = *(const uint4*)&dist_su[k * 260 + nq];
        *(uint4*)&g_whl[(size_t)(b * KDIM + k) * NPIX + n0 + nq] = v;
    }
}

// ============================================================================
// Kernel 2 (warp-MMA): out[b][k][c] = sum_n w[k][n]*x[c][n] - wsum[k]*cw[k][c]
// grid (4 c-tiles, 32 b), 256 threads = 8 warps.
// CTA tile: M=128 c-rows, N=32 k-cols, full n contraction in 64-chunks.
// Warp tile 32c x 16k = 2x2 m16n8k16 frags; 3 MMAs (hh, hl, lh) per frag pair.
// ============================================================================
__global__ __launch_bounds__(256) void enc_k2m(
    const float* __restrict__ x,
    const float* __restrict__ cw,
    float* __restrict__ out)
{
    __shared__ __align__(16) __nv_bfloat16 xh_s[128 * 72];  // 18432 B
    __shared__ __align__(16) __nv_bfloat16 xl_s[128 * 72];
    __shared__ __align__(16) __nv_bfloat16 wh_s[32 * 72];   // 4608 B
    __shared__ __align__(16) __nv_bfloat16 wl_s[32 * 72];
    __shared__ float wsum_s[KDIM];

    const int t = threadIdx.x;
    const int w = t >> 5, lane = t & 31;
    const int g = lane >> 2, tg = lane & 3;
    const int b = blockIdx.y;
    const int c0 = blockIdx.x * 128;
    const int mb = (w & 3) * 32;      // warp m (c) base
    const int nb = (w >> 2) * 16;     // warp n (k) base

    if (t < KDIM) {
        float s = 0.f;
        #pragma unroll
        for (int j = 0; j < 16; ++j)
            s += g_wsum[((size_t)b * 16 + j) * KDIM + t];
        wsum_s[t] = s;
    }

    float d[2][2][4];
    #pragma unroll
    for (int mi = 0; mi < 2; ++mi)
        #pragma unroll
        for (int ni = 0; ni < 2; ++ni)
            #pragma unroll
            for (int r = 0; r < 4; ++r) d[mi][ni][r] = 0.f;

    for (int n0 = 0; n0 < NPIX; n0 += 64) {
        __syncthreads();
        // ---- stage x -> bf16 hi/lo, [c][n] pitch 72 ----
        #pragma unroll
        for (int i = 0; i < 8; ++i) {
            int idx = t + 256 * i;
            int cl = idx >> 4, nq = (idx & 15) * 4;
            float4 v = *(const float4*)(
                x + (size_t)(b * CDIM + c0 + cl) * NPIX + n0 + nq);
            unsigned h0 = pk_bf16x2(v.x, v.y);
            unsigned h1 = pk_bf16x2(v.z, v.w);
            float hx = __uint_as_float(h0 << 16);
            float hy = __uint_as_float(h0 & 0xFFFF0000u);
            float hz = __uint_as_float(h1 << 16);
            float hw = __uint_as_float(h1 & 0xFFFF0000u);
            unsigned l0 = pk_bf16x2(v.x - hx, v.y - hy);
            unsigned l1 = pk_bf16x2(v.z - hz, v.w - hw);
            *(uint2*)&xh_s[cl * 72 + nq] = make_uint2(h0, h1);
            *(uint2*)&xl_s[cl * 72 + nq] = make_uint2(l0, l1);
        }
        // ---- stage w: unpack {hi,lo} words, [k][n] pitch 72 ----
        #pragma unroll
        for (int i = 0; i < 2; ++i) {
            int idx = t + 256 * i;
            int kl = idx >> 4, nq = (idx & 15) * 4;
            uint4 p = *(const uint4*)&g_whl[(size_t)(b * KDIM + kl) * NPIX + n0 + nq];
            unsigned h01 = __byte_perm(p.x, p.y, 0x5410);
            unsigned l01 = __byte_perm(p.x, p.y, 0x7632);
            unsigned h23 = __byte_perm(p.z, p.w, 0x5410);
            unsigned l23 = __byte_perm(p.z, p.w, 0x7632);
            *(uint2*)&wh_s[kl * 72 + nq] = make_uint2(h01, h23);
            *(uint2*)&wl_s[kl * 72 + nq] = make_uint2(l01, l23);
        }
        __syncthreads();

        // ---- 4 k16-steps over this 64n chunk ----
        #pragma unroll
        for (int s = 0; s < 4; ++s) {
            const int kk = s * 16 + 2 * tg;
            unsigned ah[2][4], al[2][4], bh[2][2], bl[2][2];
            #pragma unroll
            for (int mi = 0; mi < 2; ++mi) {
                const int r0 = (mb + mi * 16 + g) * 72 + kk;
                const int r1 = r0 + 8 * 72;
                ah[mi][0] = *(const unsigned*)&xh_s[r0];
                ah[mi][1] = *(const unsigned*)&xh_s[r1];
                ah[mi][2] = *(const unsigned*)&xh_s[r0 + 8];
                ah[mi][3] = *(const unsigned*)&xh_s[r1 + 8];
                al[mi][0] = *(const unsigned*)&xl_s[r0];
                al[mi][1] = *(const unsigned*)&xl_s[r1];
                al[mi][2] = *(const unsigned*)&xl_s[r0 + 8];
                al[mi][3] = *(const unsigned*)&xl_s[r1 + 8];
            }
            #pragma unroll
            for (int ni = 0; ni < 2; ++ni) {
                const int q0 = (nb + ni * 8 + g) * 72 + kk;
                bh[ni][0] = *(const unsigned*)&wh_s[q0];
                bh[ni][1] = *(const unsigned*)&wh_s[q0 + 8];
                bl[ni][0] = *(const unsigned*)&wl_s[q0];
                bl[ni][1] = *(const unsigned*)&wl_s[q0 + 8];
            }
            #pragma unroll
            for (int mi = 0; mi < 2; ++mi)
                #pragma unroll
                for (int ni = 0; ni < 2; ++ni) {
                    mma_bf16(d[mi][ni], ah[mi][0], ah[mi][1], ah[mi][2],
                             ah[mi][3], bh[ni][0], bh[ni][1]);
                    mma_bf16(d[mi][ni], ah[mi][0], ah[mi][1], ah[mi][2],
                             ah[mi][3], bl[ni][0], bl[ni][1]);
                    mma_bf16(d[mi][ni], al[mi][0], al[mi][1], al[mi][2],
                             al[mi][3], bh[ni][0], bh[ni][1]);
                }
        }
    }

    // ---- epilogue: out = acc - wsum*cw ----
    #pragma unroll
    for (int mi = 0; mi < 2; ++mi)
        #pragma unroll
        for (int ni = 0; ni < 2; ++ni) {
            const int k0 = nb + ni * 8 + 2 * tg;
            const int cA = c0 + mb + mi * 16 + g;
            const int cB = cA + 8;
            const float* dd = d[mi][ni];
            out[(size_t)(b * KDIM + k0) * CDIM + cA] =
                dd[0] - wsum_s[k0] * cw[k0 * CDIM + cA];
            out[(size_t)(b * KDIM + k0 + 1) * CDIM + cA] =
                dd[1] - wsum_s[k0 + 1] * cw[(k0 + 1) * CDIM + cA];
            out[(size_t)(b * KDIM + k0) * CDIM + cB] =
                dd[2] - wsum_s[k0] * cw[k0 * CDIM + cB];
            out[(size_t)(b * KDIM + k0 + 1) * CDIM + cB] =
                dd[3] - wsum_s[k0 + 1] * cw[(k0 + 1) * CDIM + cB];
        }
}

// ============================================================================
extern "C" void kernel_launch(void* const* d_in, const int* in_sizes, int n_in,
                              void* d_out, int out_size)
{
    (void)in_sizes; (void)n_in; (void)out_size;
    const float* x     = (const float*)d_in[0];   // [32,512,64,64]
    const float* cw    = (const float*)d_in[1];   // [32,512]
    const float* scale = (const float*)d_in[2];   // [32]
    float* out = (float*)d_out;                   // [32,32,512]

    enc_k1 <<<dim3(16, 32), 256>>>(x, cw, scale);
    enc_k2m<<<dim3(4, 32), 256>>>(x, cw, out);
}

// round 9
// speedup vs baseline: 1.8141x; 1.8141x over previous
#include <cuda_runtime.h>
#include <cuda_bf16.h>
#include <cstdint>

#define BDIM 32
#define CDIM 512
#define KDIM 32
#define NPIX 4096   // 64*64

// w packed per element: u32 = { bf16 hi (low 16b), bf16 lo (high 16b) }
__device__ unsigned g_whl[BDIM * KDIM * NPIX];     // 16 MiB
__device__ float g_part[4 * BDIM * KDIM * CDIM];   // 8 MiB

// pack {lo_elem -> low 16, hi_elem -> high 16}
__device__ __forceinline__ unsigned pk_bf16x2(float lo, float hi) {
    unsigned r;
    asm("cvt.rn.bf16x2.f32 %0, %1, %2;" : "=r"(r) : "f"(hi), "f"(lo));
    return r;
}

// ---------- warp mma (legacy HMMA path, no 'a'-feature needed) ----------
__device__ __forceinline__ void mma_bf16(float* d,
                                         unsigned a0, unsigned a1,
                                         unsigned a2, unsigned a3,
                                         unsigned b0, unsigned b1) {
    asm volatile(
        "mma.sync.aligned.m16n8k16.row.col.f32.bf16.bf16.f32 "
        "{%0,%1,%2,%3}, {%4,%5,%6,%7}, {%8,%9}, {%0,%1,%2,%3};"
        : "+f"(d[0]), "+f"(d[1]), "+f"(d[2]), "+f"(d[3])
        : "r"(a0), "r"(a1), "r"(a2), "r"(a3), "r"(b0), "r"(b1));
}
__device__ __forceinline__ void mma_tf32(float* d,
                                         unsigned a0, unsigned a1,
                                         unsigned a2, unsigned a3,
                                         unsigned b0, unsigned b1) {
    asm volatile(
        "mma.sync.aligned.m16n8k8.row.col.f32.tf32.tf32.f32 "
        "{%0,%1,%2,%3}, {%4,%5,%6,%7}, {%8,%9}, {%0,%1,%2,%3};"
        : "+f"(d[0]), "+f"(d[1]), "+f"(d[2]), "+f"(d[3])
        : "r"(a0), "r"(a1), "r"(a2), "r"(a3), "r"(b0), "r"(b1));
}

// ============================================================================
// Kernel 1 (tf32 MMA): dist[k][n] = scale_k*(x2_n - 2*xc + c2_k), softmax over
// k, pack w hi/lo -> g_whl. grid (16 n-tiles, 32 b), 256 thr = 8 warps.
// CTA: 256 pixels x 32 k x 512 c (16 chunks of 32c).
// Warp tile: 32 pixels (2 m16) x 32 k (4 n8). x2/c2 exact fp32; only xc tf32.
// ============================================================================
__global__ __launch_bounds__(256) void enc_k1(
    const float* __restrict__ x,
    const float* __restrict__ cw,
    const float* __restrict__ scale)
{
    // pool: x_s [32c][264] during GEMM; dist [32k][260] in epilogue
    __shared__ __align__(16) float pool[32 * 264];
    __shared__ __align__(16) float cw_s[32 * 40];
    __shared__ float x2_s[256];
    __shared__ float c2_s[KDIM];
    __shared__ float sc_s[KDIM];

    float* dist_s = pool;
    unsigned* dist_su = (unsigned*)pool;

    const int t    = threadIdx.x;
    const int b    = blockIdx.y;
    const int n0   = blockIdx.x * 256;
    const int lane = t & 31, w = t >> 5;
    const int g  = lane >> 2;    // row group 0..7
    const int tg = lane & 3;     // thread-in-group

    // ---- c2[k] precompute (x2_s as scratch) ----
    {
        const int k = t >> 3, seg = t & 7;
        const float4* p = (const float4*)(cw + k * CDIM + seg * 64);
        float s = 0.f;
        #pragma unroll
        for (int i = 0; i < 16; ++i) {
            float4 v = p[i];
            s += v.x * v.x + v.y * v.y + v.z * v.z + v.w * v.w;
        }
        x2_s[t] = s;
        if (t < KDIM) sc_s[t] = scale[t];
        __syncthreads();
        if (t < KDIM) {
            float s2 = 0.f;
            #pragma unroll
            for (int j = 0; j < 8; ++j) s2 += x2_s[t * 8 + j];
            c2_s[t] = s2;
        }
    }

    float dacc[2][4][4];
    #pragma unroll
    for (int mi = 0; mi < 2; ++mi)
        #pragma unroll
        for (int ni = 0; ni < 4; ++ni)
            #pragma unroll
            for (int r = 0; r < 4; ++r) dacc[mi][ni][r] = 0.f;
    float x2a = 0.f;

    const float* xb = x + (size_t)b * CDIM * NPIX + n0;

    for (int c0 = 0; c0 < CDIM; c0 += 32) {
        __syncthreads();
        // stage x [32c][264-pitch]
        #pragma unroll
        for (int i = 0; i < 8; ++i) {
            int idx = t + 256 * i;
            int cb = idx >> 6, nq = (idx & 63) * 4;
            float4 v = *(const float4*)(xb + (size_t)(c0 + cb) * NPIX + nq);
            *(float4*)(pool + cb * 264 + nq) = v;
        }
        // stage cw chunk [32k][40-pitch]
        {
            int k = t >> 3, cq = (t & 7) * 4;
            float4 v = *(const float4*)(cw + k * CDIM + c0 + cq);
            *(float4*)(cw_s + k * 40 + cq) = v;
        }
        __syncthreads();

        // exact fp32 x2 partial (thread t owns pixel t)
        #pragma unroll 8
        for (int cb = 0; cb < 32; ++cb) {
            float v = pool[cb * 264 + t];
            x2a = fmaf(v, v, x2a);
        }

        // 4 k8-steps over 32 c
        #pragma unroll
        for (int s = 0; s < 4; ++s) {
            const int col = s * 8 + tg;
            unsigned bb0[4], bb1[4];
            #pragma unroll
            for (int ni = 0; ni < 4; ++ni) {
                const int ba = (ni * 8 + g) * 40 + s * 8 + tg;
                bb0[ni] = __float_as_uint(cw_s[ba]);
                bb1[ni] = __float_as_uint(cw_s[ba + 4]);
            }
            #pragma unroll
            for (int mi = 0; mi < 2; ++mi) {
                const int row = w * 32 + mi * 16 + g;
                unsigned a0 = __float_as_uint(pool[col * 264 + row]);
                unsigned a1 = __float_as_uint(pool[col * 264 + row + 8]);
                unsigned a2 = __float_as_uint(pool[(col + 4) * 264 + row]);
                unsigned a3 = __float_as_uint(pool[(col + 4) * 264 + row + 8]);
                #pragma unroll
                for (int ni = 0; ni < 4; ++ni)
                    mma_tf32(dacc[mi][ni], a0, a1, a2, a3, bb0[ni], bb1[ni]);
            }
        }
    }

    __syncthreads();             // all MMA smem reads complete
    x2_s[t] = x2a;
    __syncthreads();

    // dist = sc*(x2 - 2*xc + c2) -> pool [k][260]
    #pragma unroll
    for (int mi = 0; mi < 2; ++mi) {
        const int nr = w * 32 + mi * 16 + g;
        #pragma unroll
        for (int ni = 0; ni < 4; ++ni) {
            const int k0 = ni * 8 + 2 * tg;
            const float* dd = dacc[mi][ni];
            dist_s[k0 * 260 + nr] =
                sc_s[k0] * (x2_s[nr] - 2.f * dd[0] + c2_s[k0]);
            dist_s[(k0 + 1) * 260 + nr] =
                sc_s[k0 + 1] * (x2_s[nr] - 2.f * dd[1] + c2_s[k0 + 1]);
            dist_s[k0 * 260 + nr + 8] =
                sc_s[k0] * (x2_s[nr + 8] - 2.f * dd[2] + c2_s[k0]);
            dist_s[(k0 + 1) * 260 + nr + 8] =
                sc_s[k0 + 1] * (x2_s[nr + 8] - 2.f * dd[3] + c2_s[k0 + 1]);
        }
    }
    __syncthreads();

    // per-pixel softmax (pixel = t), pack {hi,lo} in place (own column only)
    {
        float d[KDIM];
        #pragma unroll
        for (int k = 0; k < KDIM; ++k) d[k] = dist_s[k * 260 + t];
        float m = d[0];
        #pragma unroll
        for (int k = 1; k < KDIM; ++k) m = fmaxf(m, d[k]);
        float sum = 0.f;
        #pragma unroll
        for (int k = 0; k < KDIM; ++k) { d[k] = __expf(d[k] - m); sum += d[k]; }
        const float inv = 1.0f / sum;
        #pragma unroll
        for (int k = 0; k < KDIM; ++k) {
            float wv = d[k] * inv;
            __nv_bfloat16 h = __float2bfloat16(wv);
            float hf = __bfloat162float(h);
            __nv_bfloat16 l = __float2bfloat16(wv - hf);
            unsigned word = (unsigned)__bfloat16_as_ushort(h) |
                            ((unsigned)__bfloat16_as_ushort(l) << 16);
            dist_su[k * 260 + t] = word;
        }
    }
    __syncthreads();

    // vectorized global store (STG.128)
    #pragma unroll
    for (int j = 0; j < 8; ++j) {
        int idx = t + 256 * j;
        int k = idx >> 6, nq = (idx & 63) * 4;
        uint4 v = *(const uint4*)&dist_su[k * 260 + nq];
        *(uint4*)&g_whl[(size_t)(b * KDIM + k) * NPIX + n0 + nq] = v;
    }
}

// ============================================================================
// Kernel 2 (warp-MMA): partial[s][b][k][c] = sum_{n in slice} w[k][n]*x[c][n]
// grid (4 c-tiles, 4 n-splits, 32 b) = 512 CTAs, 256 thr = 8 warps.
// CTA tile: M=128 c, N=32 k, 1024 n in 16 chunks of 64.
// Warp tile 32c x 16k = 2x2 m16n8k16; 3 MMAs (hh, hl, lh) per frag pair.
// ============================================================================
__global__ __launch_bounds__(256) void enc_k2m(const float* __restrict__ x)
{
    __shared__ __align__(16) __nv_bfloat16 xh_s[128 * 72];
    __shared__ __align__(16) __nv_bfloat16 xl_s[128 * 72];
    __shared__ __align__(16) __nv_bfloat16 wh_s[32 * 72];
    __shared__ __align__(16) __nv_bfloat16 wl_s[32 * 72];

    const int t = threadIdx.x;
    const int w = t >> 5, lane = t & 31;
    const int g = lane >> 2, tg = lane & 3;
    const int b = blockIdx.z;
    const int sp = blockIdx.y;
    const int c0 = blockIdx.x * 128;
    const int mb = (w & 3) * 32;      // warp m (c) base
    const int nb = (w >> 2) * 16;     // warp n (k) base

    float d[2][2][4];
    #pragma unroll
    for (int mi = 0; mi < 2; ++mi)
        #pragma unroll
        for (int ni = 0; ni < 2; ++ni)
            #pragma unroll
            for (int r = 0; r < 4; ++r) d[mi][ni][r] = 0.f;

    const int nbeg = sp * 1024;
    for (int n0 = nbeg; n0 < nbeg + 1024; n0 += 64) {
        __syncthreads();
        // ---- stage x -> bf16 hi/lo, [c][n] pitch 72 ----
        #pragma unroll
        for (int i = 0; i < 8; ++i) {
            int idx = t + 256 * i;
            int cl = idx >> 4, nq = (idx & 15) * 4;
            float4 v = *(const float4*)(
                x + (size_t)(b * CDIM + c0 + cl) * NPIX + n0 + nq);
            unsigned h0 = pk_bf16x2(v.x, v.y);
            unsigned h1 = pk_bf16x2(v.z, v.w);
            float hx = __uint_as_float(h0 << 16);
            float hy = __uint_as_float(h0 & 0xFFFF0000u);
            float hz = __uint_as_float(h1 << 16);
            float hw = __uint_as_float(h1 & 0xFFFF0000u);
            unsigned l0 = pk_bf16x2(v.x - hx, v.y - hy);
            unsigned l1 = pk_bf16x2(v.z - hz, v.w - hw);
            *(uint2*)&xh_s[cl * 72 + nq] = make_uint2(h0, h1);
            *(uint2*)&xl_s[cl * 72 + nq] = make_uint2(l0, l1);
        }
        // ---- stage w: unpack {hi,lo} words, [k][n] pitch 72 ----
        #pragma unroll
        for (int i = 0; i < 2; ++i) {
            int idx = t + 256 * i;
            int kl = idx >> 4, nq = (idx & 15) * 4;
            uint4 p = *(const uint4*)&g_whl[(size_t)(b * KDIM + kl) * NPIX + n0 + nq];
            unsigned h01 = __byte_perm(p.x, p.y, 0x5410);
            unsigned l01 = __byte_perm(p.x, p.y, 0x7632);
            unsigned h23 = __byte_perm(p.z, p.w, 0x5410);
            unsigned l23 = __byte_perm(p.z, p.w, 0x7632);
            *(uint2*)&wh_s[kl * 72 + nq] = make_uint2(h01, h23);
            *(uint2*)&wl_s[kl * 72 + nq] = make_uint2(l01, l23);
        }
        __syncthreads();

        // ---- 4 k16-steps over this 64n chunk ----
        #pragma unroll
        for (int s = 0; s < 4; ++s) {
            const int kk = s * 16 + 2 * tg;
            unsigned ah[2][4], al[2][4], bh[2][2], bl[2][2];
            #pragma unroll
            for (int mi = 0; mi < 2; ++mi) {
                const int r0 = (mb + mi * 16 + g) * 72 + kk;
                const int r1 = r0 + 8 * 72;
                ah[mi][0] = *(const unsigned*)&xh_s[r0];
                ah[mi][1] = *(const unsigned*)&xh_s[r1];
                ah[mi][2] = *(const unsigned*)&xh_s[r0 + 8];
                ah[mi][3] = *(const unsigned*)&xh_s[r1 + 8];
                al[mi][0] = *(const unsigned*)&xl_s[r0];
                al[mi][1] = *(const unsigned*)&xl_s[r1];
                al[mi][2] = *(const unsigned*)&xl_s[r0 + 8];
                al[mi][3] = *(const unsigned*)&xl_s[r1 + 8];
            }
            #pragma unroll
            for (int ni = 0; ni < 2; ++ni) {
                const int q0 = (nb + ni * 8 + g) * 72 + kk;
                bh[ni][0] = *(const unsigned*)&wh_s[q0];
                bh[ni][1] = *(const unsigned*)&wh_s[q0 + 8];
                bl[ni][0] = *(const unsigned*)&wl_s[q0];
                bl[ni][1] = *(const unsigned*)&wl_s[q0 + 8];
            }
            #pragma unroll
            for (int mi = 0; mi < 2; ++mi)
                #pragma unroll
                for (int ni = 0; ni < 2; ++ni) {
                    mma_bf16(d[mi][ni], ah[mi][0], ah[mi][1], ah[mi][2],
                             ah[mi][3], bh[ni][0], bh[ni][1]);
                    mma_bf16(d[mi][ni], ah[mi][0], ah[mi][1], ah[mi][2],
                             ah[mi][3], bl[ni][0], bl[ni][1]);
                    mma_bf16(d[mi][ni], al[mi][0], al[mi][1], al[mi][2],
                             al[mi][3], bh[ni][0], bh[ni][1]);
                }
        }
    }

    // ---- store partials ----
    float* pb = g_part + ((size_t)sp * BDIM + b) * KDIM * CDIM;
    #pragma unroll
    for (int mi = 0; mi < 2; ++mi)
        #pragma unroll
        for (int ni = 0; ni < 2; ++ni) {
            const int k0 = nb + ni * 8 + 2 * tg;
            const int cA = c0 + mb + mi * 16 + g;
            const int cB = cA + 8;
            const float* dd = d[mi][ni];
            pb[(size_t)k0 * CDIM + cA]       = dd[0];
            pb[(size_t)(k0 + 1) * CDIM + cA] = dd[1];
            pb[(size_t)k0 * CDIM + cB]       = dd[2];
            pb[(size_t)(k0 + 1) * CDIM + cB] = dd[3];
        }
}

// ============================================================================
// Kernel 3: out[b][k][c] = sum_s part - wsum[b][k]*cw[k][c]
// wsum computed exactly from packed w (hi+lo). grid (32 k, 32 b), 128 thr.
// ============================================================================
__global__ __launch_bounds__(128) void enc_red(const float* __restrict__ cw,
                                               float* __restrict__ out)
{
    __shared__ float red[4];
    const int t = threadIdx.x;
    const int k = blockIdx.x, b = blockIdx.y;

    const uint4* wp = (const uint4*)(g_whl + ((size_t)b * KDIM + k) * NPIX);
    float s = 0.f;
    #pragma unroll
    for (int i = 0; i < 8; ++i) {
        uint4 v = wp[t + 128 * i];
        s += __uint_as_float(v.x << 16) + __uint_as_float(v.x & 0xFFFF0000u);
        s += __uint_as_float(v.y << 16) + __uint_as_float(v.y & 0xFFFF0000u);
        s += __uint_as_float(v.z << 16) + __uint_as_float(v.z & 0xFFFF0000u);
        s += __uint_as_float(v.w << 16) + __uint_as_float(v.w & 0xFFFF0000u);
    }
    #pragma unroll
    for (int o = 16; o > 0; o >>= 1) s += __shfl_xor_sync(0xffffffffu, s, o);
    if ((t & 31) == 0) red[t >> 5] = s;
    __syncthreads();
    const float ws = red[0] + red[1] + red[2] + red[3];

    const int c = 4 * t;
    const size_t kc = ((size_t)b * KDIM + k) * CDIM + c;
    float4 p = *(const float4*)(g_part + kc);
    #pragma unroll
    for (int sp = 1; sp < 4; ++sp) {
        float4 q = *(const float4*)(g_part + (size_t)sp * BDIM * KDIM * CDIM + kc);
        p.x += q.x; p.y += q.y; p.z += q.z; p.w += q.w;
    }
    float4 cv = *(const float4*)(cw + k * CDIM + c);
    float4 o4;
    o4.x = p.x - ws * cv.x;
    o4.y = p.y - ws * cv.y;
    o4.z = p.z - ws * cv.z;
    o4.w = p.w - ws * cv.w;
    *(float4*)(out + kc) = o4;
}

// ============================================================================
extern "C" void kernel_launch(void* const* d_in, const int* in_sizes, int n_in,
                              void* d_out, int out_size)
{
    (void)in_sizes; (void)n_in; (void)out_size;
    const float* x     = (const float*)d_in[0];   // [32,512,64,64]
    const float* cw    = (const float*)d_in[1];   // [32,512]
    const float* scale = (const float*)d_in[2];   // [32]
    float* out = (float*)d_out;                   // [32,32,512]

    enc_k1 <<<dim3(16, 32), 256>>>(x, cw, scale);
    enc_k2m<<<dim3(4, 4, 32), 256>>>(x);
    enc_red<<<dim3(32, 32), 128>>>(cw, out);
}

// round 13
// speedup vs baseline: 2.3007x; 1.2682x over previous
#include <cuda_runtime.h>
#include <cuda_bf16.h>
#include <cstdint>

#define BDIM 32
#define CDIM 512
#define KDIM 32
#define NPIX 4096   // 64*64

__device__ float g_w[BDIM * KDIM * NPIX];          // softmax weights fp32, 16 MiB
__device__ float g_part[4 * BDIM * KDIM * CDIM];   // k2 partials, 8 MiB

// ---------- warp mma (legacy HMMA path, no 'a'-feature needed) ----------
__device__ __forceinline__ void mma_tf32(float* d,
                                         unsigned a0, unsigned a1,
                                         unsigned a2, unsigned a3,
                                         unsigned b0, unsigned b1) {
    asm volatile(
        "mma.sync.aligned.m16n8k8.row.col.f32.tf32.tf32.f32 "
        "{%0,%1,%2,%3}, {%4,%5,%6,%7}, {%8,%9}, {%0,%1,%2,%3};"
        : "+f"(d[0]), "+f"(d[1]), "+f"(d[2]), "+f"(d[3])
        : "r"(a0), "r"(a1), "r"(a2), "r"(a3), "r"(b0), "r"(b1));
}

// ---------- cp.async ----------
__device__ __forceinline__ uint32_t smem_u32(const void* p) {
    uint32_t a;
    asm("{ .reg .u64 t; cvta.to.shared.u64 t, %1; cvt.u32.u64 %0, t; }"
        : "=r"(a) : "l"(p));
    return a;
}
#define CPA16(dst, src) \
    asm volatile("cp.async.cg.shared.global [%0], [%1], 16;" \
                 :: "r"(dst), "l"(src) : "memory")
#define CP_COMMIT() asm volatile("cp.async.commit_group;" ::: "memory")
#define CP_WAIT2()  asm volatile("cp.async.wait_group 2;" ::: "memory")
#define CP_WAIT1()  asm volatile("cp.async.wait_group 1;" ::: "memory")
#define CP_WAIT0()  asm volatile("cp.async.wait_group 0;" ::: "memory")

#define TF32_MASK 0xFFFFE000u

// ============================================================================
// Kernel 1 (tf32 MMA + cp.async x3): dist = scale*(x2 - 2*xc + c2), softmax,
// w (fp32) -> g_w. grid (16 n-tiles, 32 b), 256 thr = 8 warps.
// CTA: 256 pixels x 32 k x 512 c in 32 chunks of 16 c, 3-stage pipeline.
// dyn smem floats: xbuf 3*16*264 = 12672 | cwbuf 3*32*20 = 1920  (58368 B)
// epilogue reuses xbuf region as dist_s [32k][260].
// ============================================================================
__global__ __launch_bounds__(256) void enc_k1(
    const float* __restrict__ x,
    const float* __restrict__ cw,
    const float* __restrict__ scale)
{
    extern __shared__ float dyn[];
    float* dist_s = dyn;                 // epilogue alias
    __shared__ float x2_s[256];
    __shared__ float c2_s[KDIM];
    __shared__ float sc_s[KDIM];

    const int t    = threadIdx.x;
    const int b    = blockIdx.y;
    const int n0   = blockIdx.x * 256;
    const int lane = t & 31, w = t >> 5;
    const int g  = lane >> 2;
    const int tg = lane & 3;

    const uint32_t sb = smem_u32(dyn);
    const float* xb = x + (size_t)b * CDIM * NPIX + n0;

    // ---- c2[k] precompute (x2_s as scratch) ----
    {
        const int k = t >> 3, seg = t & 7;
        const float4* p = (const float4*)(cw + k * CDIM + seg * 64);
        float s = 0.f;
        #pragma unroll
        for (int i = 0; i < 16; ++i) {
            float4 v = p[i];
            s += v.x * v.x + v.y * v.y + v.z * v.z + v.w * v.w;
        }
        x2_s[t] = s;
        if (t < KDIM) sc_s[t] = scale[t];
        __syncthreads();
        if (t < KDIM) {
            float s2 = 0.f;
            #pragma unroll
            for (int j = 0; j < 8; ++j) s2 += x2_s[t * 8 + j];
            c2_s[t] = s2;
        }
        __syncthreads();
    }

    // ---- issue helper (chunk ch -> slot) ----
    auto issue = [&](int ch, int slot) {
        const int c0 = ch * 16;
        const uint32_t xd = sb + (uint32_t)(slot * 4224) * 4u;
        #pragma unroll
        for (int i = 0; i < 4; ++i) {
            int idx = t + 256 * i;
            int cb = idx >> 6, nq = (idx & 63) * 4;
            CPA16(xd + (uint32_t)(cb * 264 + nq) * 4u,
                  xb + (size_t)(c0 + cb) * NPIX + nq);
        }
        if (t < 128) {
            int k = t >> 2, cq = (t & 3) * 4;
            const uint32_t cd = sb + (uint32_t)(12672 + slot * 640) * 4u;
            CPA16(cd + (uint32_t)(k * 20 + cq) * 4u,
                  cw + k * CDIM + c0 + cq);
        }
    };

    float dacc[2][4][4];
    #pragma unroll
    for (int mi = 0; mi < 2; ++mi)
        #pragma unroll
        for (int ni = 0; ni < 4; ++ni)
            #pragma unroll
            for (int r = 0; r < 4; ++r) dacc[mi][ni][r] = 0.f;
    float x2a = 0.f;

    // prologue: chunks 0..2
    #pragma unroll
    for (int p = 0; p < 3; ++p) { issue(p, p); CP_COMMIT(); }

    for (int ch = 0; ch < 32; ++ch) {
        if (ch < 29) CP_WAIT2(); else CP_WAIT0();
        __syncthreads();
        const int slot = ch % 3;
        const float* xs  = dyn + slot * 4224;
        const float* cws = dyn + 12672 + slot * 640;

        // exact fp32 x2 partial (thread t owns pixel t)
        #pragma unroll
        for (int cb = 0; cb < 16; ++cb) {
            float v = xs[cb * 264 + t];
            x2a = fmaf(v, v, x2a);
        }

        // 2 k8-steps over 16 c
        #pragma unroll
        for (int s = 0; s < 2; ++s) {
            const int col = s * 8 + tg;
            unsigned bb0[4], bb1[4];
            #pragma unroll
            for (int ni = 0; ni < 4; ++ni) {
                const int ba = (ni * 8 + g) * 20 + s * 8 + tg;
                bb0[ni] = __float_as_uint(cws[ba]);
                bb1[ni] = __float_as_uint(cws[ba + 4]);
            }
            #pragma unroll
            for (int mi = 0; mi < 2; ++mi) {
                const int row = w * 32 + mi * 16 + g;
                unsigned a0 = __float_as_uint(xs[col * 264 + row]);
                unsigned a1 = __float_as_uint(xs[col * 264 + row + 8]);
                unsigned a2 = __float_as_uint(xs[(col + 4) * 264 + row]);
                unsigned a3 = __float_as_uint(xs[(col + 4) * 264 + row + 8]);
                #pragma unroll
                for (int ni = 0; ni < 4; ++ni)
                    mma_tf32(dacc[mi][ni], a0, a1, a2, a3, bb0[ni], bb1[ni]);
            }
        }
        __syncthreads();
        if (ch + 3 < 32) { issue(ch + 3, (ch + 3) % 3); CP_COMMIT(); }
    }

    x2_s[t] = x2a;
    __syncthreads();

    // dist = sc*(x2 - 2*xc + c2) -> dist_s [k][260]
    #pragma unroll
    for (int mi = 0; mi < 2; ++mi) {
        const int nr = w * 32 + mi * 16 + g;
        #pragma unroll
        for (int ni = 0; ni < 4; ++ni) {
            const int k0 = ni * 8 + 2 * tg;
            const float* dd = dacc[mi][ni];
            dist_s[k0 * 260 + nr] =
                sc_s[k0] * (x2_s[nr] - 2.f * dd[0] + c2_s[k0]);
            dist_s[(k0 + 1) * 260 + nr] =
                sc_s[k0 + 1] * (x2_s[nr] - 2.f * dd[1] + c2_s[k0 + 1]);
            dist_s[k0 * 260 + nr + 8] =
                sc_s[k0] * (x2_s[nr + 8] - 2.f * dd[2] + c2_s[k0]);
            dist_s[(k0 + 1) * 260 + nr + 8] =
                sc_s[k0 + 1] * (x2_s[nr + 8] - 2.f * dd[3] + c2_s[k0 + 1]);
        }
    }
    __syncthreads();

    // per-pixel softmax (pixel = t), write w fp32 in place
    {
        float d[KDIM];
        #pragma unroll
        for (int k = 0; k < KDIM; ++k) d[k] = dist_s[k * 260 + t];
        float m = d[0];
        #pragma unroll
        for (int k = 1; k < KDIM; ++k) m = fmaxf(m, d[k]);
        float sum = 0.f;
        #pragma unroll
        for (int k = 0; k < KDIM; ++k) { d[k] = __expf(d[k] - m); sum += d[k]; }
        const float inv = 1.0f / sum;
        #pragma unroll
        for (int k = 0; k < KDIM; ++k) dist_s[k * 260 + t] = d[k] * inv;
    }
    __syncthreads();

    // vectorized global store (STG.128)
    #pragma unroll
    for (int j = 0; j < 8; ++j) {
        int idx = t + 256 * j;
        int k = idx >> 6, nq = (idx & 63) * 4;
        float4 v = *(const float4*)&dist_s[k * 260 + nq];
        *(float4*)&g_w[(size_t)(b * KDIM + k) * NPIX + n0 + nq] = v;
    }
}

// ============================================================================
// Kernel 2 (tf32 hi/lo MMA + cp.async x2):
// partial[s][b][k][c] = sum_{n in slice} w[k][n]*x[c][n]
// grid (4 c-tiles, 4 n-splits, 32 b) = 512 CTAs, 256 thr = 8 warps.
// CTA tile: M=128 c, N=32 k, 1024 n in 16 chunks of 64. Raw fp32 staged via
// cp.async; hi/lo split in registers (hi = bits & 0xFFFFE000, lo = v - hi).
// 3 MMAs (hh, hl, lh) per frag pair. Warp tile 32c x 16k.
// dyn smem floats: xbuf 2*128*68 = 17408 | wbuf 2*32*68 = 4352  (87040 B)
// ============================================================================
__global__ __launch_bounds__(256) void enc_k2m(const float* __restrict__ x)
{
    extern __shared__ float dyn[];
    const int t = threadIdx.x;
    const int w = t >> 5, lane = t & 31;
    const int g = lane >> 2, tg = lane & 3;
    const int b = blockIdx.z;
    const int sp = blockIdx.y;
    const int c0 = blockIdx.x * 128;
    const int mb = (w & 3) * 32;      // warp m (c) base
    const int nb = (w >> 2) * 16;     // warp n (k) base

    const uint32_t sb = smem_u32(dyn);
    const float* xbase = x + ((size_t)b * CDIM + c0) * NPIX;
    const float* wbase = g_w + (size_t)b * KDIM * NPIX;
    const int nbeg = sp * 1024;

    auto issue = [&](int ch, int slot) {
        const int n0 = nbeg + ch * 64;
        const uint32_t xd = sb + (uint32_t)(slot * 8704) * 4u;
        #pragma unroll
        for (int i = 0; i < 8; ++i) {
            int idx = t + 256 * i;
            int cl = idx >> 4, nq = (idx & 15) * 4;
            CPA16(xd + (uint32_t)(cl * 68 + nq) * 4u,
                  xbase + (size_t)cl * NPIX + n0 + nq);
        }
        const uint32_t wd = sb + (uint32_t)(17408 + slot * 2176) * 4u;
        #pragma unroll
        for (int i = 0; i < 2; ++i) {
            int idx = t + 256 * i;
            int kl = idx >> 4, nq = (idx & 15) * 4;
            CPA16(wd + (uint32_t)(kl * 68 + nq) * 4u,
                  wbase + (size_t)kl * NPIX + n0 + nq);
        }
    };

    float d[2][2][4];
    #pragma unroll
    for (int mi = 0; mi < 2; ++mi)
        #pragma unroll
        for (int ni = 0; ni < 2; ++ni)
            #pragma unroll
            for (int r = 0; r < 4; ++r) d[mi][ni][r] = 0.f;

    issue(0, 0); CP_COMMIT();

    for (int ch = 0; ch < 16; ++ch) {
        if (ch < 15) { issue(ch + 1, (ch + 1) & 1); CP_COMMIT(); CP_WAIT1(); }
        else CP_WAIT0();
        __syncthreads();
        const float* xs = dyn + (ch & 1) * 8704;
        const float* ws = dyn + 17408 + (ch & 1) * 2176;

        #pragma unroll
        for (int s = 0; s < 8; ++s) {
            const int kk = s * 8 + tg;
            unsigned ah[2][4], al[2][4], bh[2][2], bl[2][2];
            #pragma unroll
            for (int mi = 0; mi < 2; ++mi) {
                const int r0 = (mb + mi * 16 + g) * 68 + kk;
                const int r1 = r0 + 8 * 68;
                unsigned rr[4];
                rr[0] = __float_as_uint(xs[r0]);
                rr[1] = __float_as_uint(xs[r1]);
                rr[2] = __float_as_uint(xs[r0 + 4]);
                rr[3] = __float_as_uint(xs[r1 + 4]);
                #pragma unroll
                for (int q = 0; q < 4; ++q) {
                    unsigned hb = rr[q] & TF32_MASK;
                    ah[mi][q] = hb;
                    al[mi][q] = __float_as_uint(
                        __uint_as_float(rr[q]) - __uint_as_float(hb));
                }
            }
            #pragma unroll
            for (int ni = 0; ni < 2; ++ni) {
                const int q0 = (nb + ni * 8 + g) * 68 + kk;
                unsigned r0 = __float_as_uint(ws[q0]);
                unsigned r1 = __float_as_uint(ws[q0 + 4]);
                unsigned h0 = r0 & TF32_MASK, h1 = r1 & TF32_MASK;
                bh[ni][0] = h0;
                bh[ni][1] = h1;
                bl[ni][0] = __float_as_uint(
                    __uint_as_float(r0) - __uint_as_float(h0));
                bl[ni][1] = __float_as_uint(
                    __uint_as_float(r1) - __uint_as_float(h1));
            }
            #pragma unroll
            for (int mi = 0; mi < 2; ++mi)
                #pragma unroll
                for (int ni = 0; ni < 2; ++ni) {
                    mma_tf32(d[mi][ni], ah[mi][0], ah[mi][1], ah[mi][2],
                             ah[mi][3], bh[ni][0], bh[ni][1]);
                    mma_tf32(d[mi][ni], ah[mi][0], ah[mi][1], ah[mi][2],
                             ah[mi][3], bl[ni][0], bl[ni][1]);
                    mma_tf32(d[mi][ni], al[mi][0], al[mi][1], al[mi][2],
                             al[mi][3], bh[ni][0], bh[ni][1]);
                }
        }
        __syncthreads();
    }

    // ---- store partials ----
    float* pb = g_part + ((size_t)sp * BDIM + b) * KDIM * CDIM;
    #pragma unroll
    for (int mi = 0; mi < 2; ++mi)
        #pragma unroll
        for (int ni = 0; ni < 2; ++ni) {
            const int k0 = nb + ni * 8 + 2 * tg;
            const int cA = c0 + mb + mi * 16 + g;
            const int cB = cA + 8;
            const float* dd = d[mi][ni];
            pb[(size_t)k0 * CDIM + cA]       = dd[0];
            pb[(size_t)(k0 + 1) * CDIM + cA] = dd[1];
            pb[(size_t)k0 * CDIM + cB]       = dd[2];
            pb[(size_t)(k0 + 1) * CDIM + cB] = dd[3];
        }
}

// ============================================================================
// Kernel 3: out[b][k][c] = sum_s part - wsum[b][k]*cw[k][c]
// wsum exact from fp32 g_w. grid (32 k, 32 b), 128 thr.
// ============================================================================
__global__ __launch_bounds__(128) void enc_red(const float* __restrict__ cw,
                                               float* __restrict__ out)
{
    __shared__ float red[4];
    const int t = threadIdx.x;
    const int k = blockIdx.x, b = blockIdx.y;

    const float4* wp = (const float4*)(g_w + ((size_t)b * KDIM + k) * NPIX);
    float s = 0.f;
    #pragma unroll
    for (int i = 0; i < 8; ++i) {
        float4 v = wp[t + 128 * i];
        s += (v.x + v.y) + (v.z + v.w);
    }
    #pragma unroll
    for (int o = 16; o > 0; o >>= 1) s += __shfl_xor_sync(0xffffffffu, s, o);
    if ((t & 31) == 0) red[t >> 5] = s;
    __syncthreads();
    const float ws = red[0] + red[1] + red[2] + red[3];

    const int c = 4 * t;
    const size_t kc = ((size_t)b * KDIM + k) * CDIM + c;
    float4 p = *(const float4*)(g_part + kc);
    #pragma unroll
    for (int sp = 1; sp < 4; ++sp) {
        float4 q = *(const float4*)(g_part + (size_t)sp * BDIM * KDIM * CDIM + kc);
        p.x += q.x; p.y += q.y; p.z += q.z; p.w += q.w;
    }
    float4 cv = *(const float4*)(cw + k * CDIM + c);
    float4 o4;
    o4.x = p.x - ws * cv.x;
    o4.y = p.y - ws * cv.y;
    o4.z = p.z - ws * cv.z;
    o4.w = p.w - ws * cv.w;
    *(float4*)(out + kc) = o4;
}

// ============================================================================
extern "C" void kernel_launch(void* const* d_in, const int* in_sizes, int n_in,
                              void* d_out, int out_size)
{
    (void)in_sizes; (void)n_in; (void)out_size;
    const float* x     = (const float*)d_in[0];   // [32,512,64,64]
    const float* cw    = (const float*)d_in[1];   // [32,512]
    const float* scale = (const float*)d_in[2];   // [32]
    float* out = (float*)d_out;                   // [32,32,512]

    cudaFuncSetAttribute(enc_k1, cudaFuncAttributeMaxDynamicSharedMemorySize,
                         58368);
    cudaFuncSetAttribute(enc_k2m, cudaFuncAttributeMaxDynamicSharedMemorySize,
                         87040);

    enc_k1 <<<dim3(16, 32), 256, 58368>>>(x, cw, scale);
    enc_k2m<<<dim3(4, 4, 32), 256, 87040>>>(x);
    enc_red<<<dim3(32, 32), 128>>>(cw, out);
}